// round 4
// baseline (speedup 1.0000x reference)
#include <cuda_runtime.h>
#include <cuda_bf16.h>
#include <math.h>

#define TT 4096
#define EMB 512
#define HID 2048
#define NCH 256
#define NCOLS 8192            // 4*HID
#define NCTA 128
#define HPB 16                // hidden units per CTA
#define THR 256               // 8 warps, 2 units per warp
#define NSM 27                // weight rows cached in SMEM per CTA (of 64)
#define G1S 11                // gate-1 rows in SMEM for unit u < G1S

// Static device scratch (allocation-free rule: __device__ globals only)
__device__ float g_Wt[(size_t)NCOLS * HID];     // Wt[gate*2048+j][k] = Wg[(512+k)*2048+j]
__device__ float g_Zx[(size_t)TT * NCOLS];      // input-part preactivations (+bias)
__device__ float g_hs[(size_t)TT * HID];        // hidden states per step
__device__ unsigned g_flags[NCTA * 32];         // per-CTA step flags, 128B apart

__device__ __forceinline__ unsigned ldacq(const unsigned* p) {
    unsigned v;
    asm volatile("ld.acquire.gpu.u32 %0, [%1];" : "=r"(v) : "l"(p) : "memory");
    return v;
}
__device__ __forceinline__ void fma2(unsigned long long& acc,
                                     unsigned long long w, unsigned long long h) {
    asm("fma.rn.f32x2 %0, %1, %2, %0;" : "+l"(acc) : "l"(w), "l"(h));
}
__device__ __forceinline__ float acc_sum(unsigned long long a) {
    return __uint_as_float((unsigned)a) + __uint_as_float((unsigned)(a >> 32));
}

__global__ void bar_init_kernel() {
    if (threadIdx.x < NCTA) g_flags[threadIdx.x * 32] = 0u;
}

// ---------------------------------------------------------------------------
// K0: transpose hidden-part of gate weights into row-per-output-column layout
// ---------------------------------------------------------------------------
__global__ __launch_bounds__(256) void wt_transpose_kernel(
    const float* __restrict__ W0, const float* __restrict__ W1,
    const float* __restrict__ W2, const float* __restrict__ W3)
{
    __shared__ float tile[32][33];
    int g = blockIdx.z;
    const float* W = (g == 0) ? W0 : (g == 1) ? W1 : (g == 2) ? W2 : W3;
    int k0 = blockIdx.x * 32;
    int j0 = blockIdx.y * 32;
    int tx = threadIdx.x & 31;
    int ty = threadIdx.x >> 5;

#pragma unroll
    for (int i = 0; i < 4; ++i) {
        int r = ty + i * 8;
        tile[r][tx] = W[(size_t)(EMB + k0 + r) * HID + (j0 + tx)];
    }
    __syncthreads();
#pragma unroll
    for (int i = 0; i < 4; ++i) {
        int r = ty + i * 8;
        g_Wt[((size_t)g * HID + (j0 + r)) * HID + (k0 + tx)] = tile[tx][r];
    }
}

// ---------------------------------------------------------------------------
// K1: Zx[t][g*2048+j] = emb[idx[t]] @ Wg[:512] + bg   (M=4096,N=8192,K=512)
// ---------------------------------------------------------------------------
__global__ __launch_bounds__(256) void zx_gemm_kernel(
    const int* __restrict__ idx, const float* __restrict__ emb,
    const float* __restrict__ W0, const float* __restrict__ W1,
    const float* __restrict__ W2, const float* __restrict__ W3,
    const float* __restrict__ b0, const float* __restrict__ b1,
    const float* __restrict__ b2, const float* __restrict__ b3)
{
    __shared__ float As[64][17];
    __shared__ float Bs[16][64];
    __shared__ int idx_s[64];

    int m0 = blockIdx.x * 64;
    int n0 = blockIdx.y * 64;
    int gate = n0 >> 11;
    int j0 = n0 & (HID - 1);
    const float* W = (gate == 0) ? W0 : (gate == 1) ? W1 : (gate == 2) ? W2 : W3;
    const float* bias = (gate == 0) ? b0 : (gate == 1) ? b1 : (gate == 2) ? b2 : b3;

    int tid = threadIdx.x;
    int tx = tid & 15, ty = tid >> 4;

    if (tid < 64) idx_s[tid] = idx[m0 + tid];
    __syncthreads();

    float acc[4][4] = {};
    for (int k0 = 0; k0 < EMB; k0 += 16) {
        {
            int kk = tid & 15;
            int mmb = tid >> 4;
#pragma unroll
            for (int r = 0; r < 4; ++r) {
                int mm = mmb + r * 16;
                As[mm][kk] = emb[(size_t)idx_s[mm] * EMB + k0 + kk];
            }
        }
        {
            int nn = tid & 63;
            int kkb = tid >> 6;
#pragma unroll
            for (int r = 0; r < 4; ++r) {
                int kk = kkb + r * 4;
                Bs[kk][nn] = W[(size_t)(k0 + kk) * HID + j0 + nn];
            }
        }
        __syncthreads();
#pragma unroll
        for (int kk = 0; kk < 16; ++kk) {
            float a[4];
#pragma unroll
            for (int i = 0; i < 4; ++i) a[i] = As[ty * 4 + i][kk];
            float4 bv = *(const float4*)&Bs[kk][tx * 4];
            float b[4] = {bv.x, bv.y, bv.z, bv.w};
#pragma unroll
            for (int i = 0; i < 4; ++i)
#pragma unroll
                for (int j = 0; j < 4; ++j) acc[i][j] += a[i] * b[j];
        }
        __syncthreads();
    }
#pragma unroll
    for (int i = 0; i < 4; ++i) {
        int m = m0 + ty * 4 + i;
#pragma unroll
        for (int j = 0; j < 4; ++j) {
            int n = n0 + tx * 4 + j;
            g_Zx[(size_t)m * NCOLS + n] = acc[i][j] + bias[j0 + tx * 4 + j];
        }
    }
}

// ---------------------------------------------------------------------------
// K2: persistent recurrent LSTM.
// 128 CTAs x 256 threads (8 warps). Warp w owns hidden units a=2w, b=2w+1
// (all 8 gate rows). Lane l covers k-slice l*16..(float4 stride 32 in u2).
// Gate-3 rows of both units pinned in registers (128 regs/thread).
// SMEM: gate-0 all 16 units + gate-1 units 0..10 (27 rows, 216KB).
// Streamed LDG each step: gate-2 (16 rows) + gate-1 units 11..15 (5 rows).
// h_{t-1} read directly from global (LDG) — no SMEM staging.
// f32x2 packed FMA halves FMA instruction count, identical rounding.
// Flag-array grid barrier: CTA i releases g_flags[i*32]=t+1; warp0 polls all.
// ---------------------------------------------------------------------------
#define SMEM_FLOATS (NSM * HID)
#define SMEM_BYTES (SMEM_FLOATS * 4)

typedef unsigned long long u64t;

__global__ __launch_bounds__(THR, 1) void lstm_seq_kernel(
    const float* __restrict__ hidden0, const float* __restrict__ cell0,
    float* __restrict__ dout)
{
    extern __shared__ float smem[];
    float* wc = smem;                   // [NSM][2048]

    const int cta  = blockIdx.x;
    const int tid  = threadIdx.x;
    const int w    = tid >> 5;          // warp 0..7
    const int lane = tid & 31;
    const int hid0 = cta * HPB;
    const int a = 2 * w;                // unit A (local)
    const int b = 2 * w + 1;            // unit B (local)

    // fill SMEM weight cache: slot u = gate0 row of unit u (u<16);
    // slot 16+u = gate1 row of unit u (u<11)
    for (int slot = 0; slot < NSM; ++slot) {
        int gate = (slot < 16) ? 0 : 1;
        int j    = (slot < 16) ? slot : (slot - 16);
        const float* src = g_Wt + ((size_t)gate * HID + hid0 + j) * HID;
        for (int k = tid; k < HID; k += THR) wc[slot * HID + k] = src[k];
    }

    // pin gate-3 rows of both units in registers (16 u2 each = 64 regs each)
    const ulonglong2* g3a_p = (const ulonglong2*)(g_Wt + ((size_t)3 * HID + hid0 + a) * HID);
    const ulonglong2* g3b_p = (const ulonglong2*)(g_Wt + ((size_t)3 * HID + hid0 + b) * HID);
    ulonglong2 w3a_r[16], w3b_r[16];
#pragma unroll
    for (int i = 0; i < 16; ++i) {
        w3a_r[i] = g3a_p[i * 32 + lane];
        w3b_r[i] = g3b_p[i * 32 + lane];
    }

    // cell state lives in lane 0 (unit a) and lane 1 (unit b)
    float c = 0.f;
    if (lane < 2) c = cell0[hid0 + ((lane == 0) ? a : b)];
    __syncthreads();

    // weight row pointers
    const ulonglong2* p0a = (const ulonglong2*)(wc + a * HID);
    const ulonglong2* p0b = (const ulonglong2*)(wc + b * HID);
    const ulonglong2* p1a = (a < G1S)
        ? (const ulonglong2*)(wc + (16 + a) * HID)
        : (const ulonglong2*)(g_Wt + ((size_t)1 * HID + hid0 + a) * HID);
    const ulonglong2* p1b = (b < G1S)
        ? (const ulonglong2*)(wc + (16 + b) * HID)
        : (const ulonglong2*)(g_Wt + ((size_t)1 * HID + hid0 + b) * HID);
    const ulonglong2* p2a = (const ulonglong2*)(g_Wt + ((size_t)2 * HID + hid0 + a) * HID);
    const ulonglong2* p2b = (const ulonglong2*)(g_Wt + ((size_t)2 * HID + hid0 + b) * HID);

    const unsigned my_flag_off = (unsigned)cta * 32;

    for (int t = 0; t < TT; ++t) {
        // Zx prefetch: lane0 -> unit a, lane1 -> unit b
        float zx0 = 0.f, zx1 = 0.f, zx2 = 0.f, zx3 = 0.f;
        if (lane < 2) {
            int u = (lane == 0) ? a : b;
            const float* zp = g_Zx + (size_t)t * NCOLS + hid0 + u;
            zx0 = zp[0];
            zx1 = zp[HID];
            zx2 = zp[2 * HID];
            zx3 = zp[3 * HID];
        }

        const ulonglong2* hsrc = (t == 0)
            ? (const ulonglong2*)hidden0
            : (const ulonglong2*)(g_hs + (size_t)(t - 1) * HID);

        u64t a0a = 0, a0b = 0, a1a = 0, a1b = 0;
        u64t a2a = 0, a2b = 0, a3a = 0, a3b = 0;
#pragma unroll
        for (int i = 0; i < 16; ++i) {
            int i4 = i * 32 + lane;
            ulonglong2 v2a = p2a[i4];       // LDG
            ulonglong2 v2b = p2b[i4];       // LDG
            ulonglong2 hv  = hsrc[i4];      // LDG
            ulonglong2 v1a = p1a[i4];       // LDS or LDG
            ulonglong2 v1b = p1b[i4];
            ulonglong2 v0a = p0a[i4];       // LDS
            ulonglong2 v0b = p0b[i4];
            fma2(a0a, v0a.x, hv.x); fma2(a0a, v0a.y, hv.y);
            fma2(a0b, v0b.x, hv.x); fma2(a0b, v0b.y, hv.y);
            fma2(a1a, v1a.x, hv.x); fma2(a1a, v1a.y, hv.y);
            fma2(a1b, v1b.x, hv.x); fma2(a1b, v1b.y, hv.y);
            fma2(a2a, v2a.x, hv.x); fma2(a2a, v2a.y, hv.y);
            fma2(a2b, v2b.x, hv.x); fma2(a2b, v2b.y, hv.y);
            fma2(a3a, w3a_r[i].x, hv.x); fma2(a3a, w3a_r[i].y, hv.y);
            fma2(a3b, w3b_r[i].x, hv.x); fma2(a3b, w3b_r[i].y, hv.y);
        }
        // fold pairs, butterfly reduce (all lanes get totals)
        float s0a = acc_sum(a0a), s0b = acc_sum(a0b);
        float s1a = acc_sum(a1a), s1b = acc_sum(a1b);
        float s2a = acc_sum(a2a), s2b = acc_sum(a2b);
        float s3a = acc_sum(a3a), s3b = acc_sum(a3b);
#pragma unroll
        for (int off = 16; off; off >>= 1) {
            s0a += __shfl_xor_sync(0xffffffffu, s0a, off);
            s0b += __shfl_xor_sync(0xffffffffu, s0b, off);
            s1a += __shfl_xor_sync(0xffffffffu, s1a, off);
            s1b += __shfl_xor_sync(0xffffffffu, s1b, off);
            s2a += __shfl_xor_sync(0xffffffffu, s2a, off);
            s2b += __shfl_xor_sync(0xffffffffu, s2b, off);
            s3a += __shfl_xor_sync(0xffffffffu, s3a, off);
            s3b += __shfl_xor_sync(0xffffffffu, s3b, off);
        }

        // gate math: lane0 -> unit a, lane1 -> unit b
        if (lane < 2) {
            float zf = ((lane == 0) ? s0a : s0b) + zx0;
            float zi = ((lane == 0) ? s1a : s1b) + zx1;
            float zo = ((lane == 0) ? s2a : s2b) + zx2;
            float zc = ((lane == 0) ? s3a : s3b) + zx3;
            float f  = 1.0f / (1.0f + expf(-zf));
            float i_ = 1.0f / (1.0f + expf(-zi));
            float o_ = 1.0f / (1.0f + expf(-zo));
            float gg = tanhf(zc);
            c = f * c + i_ * gg;
            float hn = o_ * tanhf(c);
            int un = hid0 + ((lane == 0) ? a : b);
            g_hs[(size_t)t * HID + un] = hn;
            if (t == TT - 1) {
                dout[(size_t)TT * NCH + un] = hn;          // h_fin
                dout[(size_t)TT * NCH + HID + un] = c;     // c_fin
            }
            __threadfence();    // make h store visible gpu-wide before flag
        }
        __syncthreads();

        // release this CTA's flag, then warp 0 waits for all CTAs
        if (tid == 0) {
            asm volatile("st.release.gpu.global.u32 [%0], %1;"
                         :: "l"(g_flags + my_flag_off), "r"((unsigned)(t + 1))
                         : "memory");
        }
        if (tid < 32) {
            const unsigned te = (unsigned)t;
            bool ok;
            do {
                ok = true;
#pragma unroll
                for (int k = 0; k < 4; ++k) {
                    unsigned v = ldacq(g_flags + (unsigned)(lane * 4 + k) * 32);
                    ok &= (v > te);
                }
            } while (!__all_sync(0xffffffffu, ok));
        }
        __syncthreads();
    }
}

// ---------------------------------------------------------------------------
// K3: out[t][n] = hs[t] @ Wout + bout.  M=4096, N=256, K=2048
// ---------------------------------------------------------------------------
__global__ __launch_bounds__(256) void out_gemm_kernel(
    const float* __restrict__ Wout, const float* __restrict__ bout,
    float* __restrict__ dout)
{
    __shared__ float As[64][17];
    __shared__ float Bs[16][64];

    int m0 = blockIdx.x * 64;
    int n0 = blockIdx.y * 64;
    int tid = threadIdx.x;
    int tx = tid & 15, ty = tid >> 4;

    float acc[4][4] = {};
    for (int k0 = 0; k0 < HID; k0 += 16) {
        {
            int kk = tid & 15;
            int mmb = tid >> 4;
#pragma unroll
            for (int r = 0; r < 4; ++r) {
                int mm = mmb + r * 16;
                As[mm][kk] = g_hs[(size_t)(m0 + mm) * HID + k0 + kk];
            }
        }
        {
            int nn = tid & 63;
            int kkb = tid >> 6;
#pragma unroll
            for (int r = 0; r < 4; ++r) {
                int kk = kkb + r * 4;
                Bs[kk][nn] = Wout[(size_t)(k0 + kk) * NCH + n0 + nn];
            }
        }
        __syncthreads();
#pragma unroll
        for (int kk = 0; kk < 16; ++kk) {
            float a[4];
#pragma unroll
            for (int i = 0; i < 4; ++i) a[i] = As[ty * 4 + i][kk];
            float4 bv = *(const float4*)&Bs[kk][tx * 4];
            float b[4] = {bv.x, bv.y, bv.z, bv.w};
#pragma unroll
            for (int i = 0; i < 4; ++i)
#pragma unroll
                for (int j = 0; j < 4; ++j) acc[i][j] += a[i] * b[j];
        }
        __syncthreads();
    }
#pragma unroll
    for (int i = 0; i < 4; ++i) {
        int m = m0 + ty * 4 + i;
#pragma unroll
        for (int j = 0; j < 4; ++j) {
            int n = n0 + tx * 4 + j;
            dout[(size_t)m * NCH + n] = acc[i][j] + bout[n];
        }
    }
}

// ---------------------------------------------------------------------------
extern "C" void kernel_launch(void* const* d_in, const int* in_sizes, int n_in,
                              void* d_out, int out_size)
{
    const int*   idx    = (const int*)d_in[0];
    const float* hidden = (const float*)d_in[1];
    const float* cell   = (const float*)d_in[2];
    const float* emb    = (const float*)d_in[3];
    const float* Wf     = (const float*)d_in[4];
    const float* bf     = (const float*)d_in[5];
    const float* Wi     = (const float*)d_in[6];
    const float* bi     = (const float*)d_in[7];
    const float* Wo     = (const float*)d_in[8];
    const float* bo     = (const float*)d_in[9];
    const float* Wc     = (const float*)d_in[10];
    const float* bc     = (const float*)d_in[11];
    const float* Wout   = (const float*)d_in[12];
    const float* bout   = (const float*)d_in[13];
    float* out = (float*)d_out;

    cudaFuncSetAttribute(lstm_seq_kernel,
                         cudaFuncAttributeMaxDynamicSharedMemorySize, SMEM_BYTES);

    bar_init_kernel<<<1, 128>>>();
    wt_transpose_kernel<<<dim3(64, 64, 4), 256>>>(Wf, Wi, Wo, Wc);
    zx_gemm_kernel<<<dim3(64, 128), 256>>>(idx, emb, Wf, Wi, Wo, Wc, bf, bi, bo, bc);
    lstm_seq_kernel<<<NCTA, THR, SMEM_BYTES>>>(hidden, cell, out);
    out_gemm_kernel<<<dim3(64, 4), 256>>>(Wout, bout, out);
}